// round 15
// baseline (speedup 1.0000x reference)
#include <cuda_runtime.h>
#include <cuda_fp16.h>
#include <math.h>
#include <stdint.h>

// Problem constants
#define NN     20000
#define NE     320000
#define HID    10
#define NIN    9
#define EF     11
#define NITER  7
#define EWT    16        // edges per warp-tile
#define TILESW (NE/EWT)  // 20000
#define NTHR   384       // 12 warps, each an independent pipeline
#define NWARP  (NTHR/32)
#define NCTA   152       // persistent CTAs

// ---------------- smem layout (byte offsets) -------------------------------
#define SB1       40
#define SB2       104
#define SA1       72     // A1 stride (elements): 144B rows -> conflict-free ldsm
#define B1_BYTES  (96*SB1*2)             // 7680
#define B2_BYTES  (96*SB2*2)             // 19968
#define B4_BYTES  (16*SB2*2)             // 3328
#define OFF_B1    0
#define OFF_B2    (OFF_B1 + B1_BYTES)    // 7680
#define OFF_B3    (OFF_B2 + B2_BYTES)    // 27648
#define OFF_B4    (OFF_B3 + B2_BYTES)    // 47616
#define OFF_BIAS  (OFF_B4 + B4_BYTES)    // 50944 (304 floats)
#define OFF_A1    (OFF_BIAS + 304*4)     // 52160
#define A1W_BYTES (EWT*SA1*2)            // 2304 per buffer
#define SMEM_REQ  (OFF_A1 + NWARP*2*A1W_BYTES)   // 52160 + 55296 = 107456

// Weight blob (fp16 hi only): B1|B2|B3|B4
#define WB1_E   (96*SB1)
#define WB2_E   (96*SB2)
#define WB_ELEMS (WB1_E + 2*WB2_E + 16*SB2)   // 25472
__device__ __align__(16) uint16_t g_wb[WB_ELEMS];
__device__ float g_h[2][NN * HID];
__device__ float g_agg[NN * EF];
__device__ int   g_tctr[NITER];

// ------------------------------ helpers ------------------------------------
__device__ __forceinline__ uint32_t smem_u32(const void* p)
{
    uint32_t a;
    asm("{ .reg .u64 t; cvta.to.shared.u64 t, %1; cvt.u32.u64 %0, t; }"
        : "=r"(a) : "l"(p));
    return a;
}

__device__ __forceinline__ void ldsm_x4(uint32_t& r0, uint32_t& r1,
                                        uint32_t& r2, uint32_t& r3, uint32_t a)
{
    asm volatile("ldmatrix.sync.aligned.m8n8.x4.shared.b16 {%0,%1,%2,%3}, [%4];"
                 : "=r"(r0), "=r"(r1), "=r"(r2), "=r"(r3) : "r"(a));
}

__device__ __forceinline__ void mma_fp16(float* d,
                                         uint32_t a0, uint32_t a1, uint32_t a2,
                                         uint32_t a3, uint32_t b0, uint32_t b1)
{
    asm volatile(
        "mma.sync.aligned.m16n8k16.row.col.f32.f16.f16.f32 "
        "{%0,%1,%2,%3},{%4,%5,%6,%7},{%8,%9},{%0,%1,%2,%3};"
        : "+f"(d[0]), "+f"(d[1]), "+f"(d[2]), "+f"(d[3])
        : "r"(a0), "r"(a1), "r"(a2), "r"(a3), "r"(b0), "r"(b1));
}

// fp16 hi/lo split of two floats (low half = first value)
__device__ __forceinline__ void pack_hilo(float a, float b, uint32_t& hw, uint32_t& lw)
{
    __half2 h2 = __floats2half2_rn(a, b);
    float ra = a - __half2float(__low2half(h2));
    float rb = b - __half2float(__high2half(h2));
    __half2 l2 = __floats2half2_rn(ra, rb);
    hw = *reinterpret_cast<uint32_t*>(&h2);
    lw = *reinterpret_cast<uint32_t*>(&l2);
}

// ---------------------------------------------------------------------------
// Setup: zero state + pack fp16(hi) weights
// ---------------------------------------------------------------------------
__global__ void setup_kernel(const float* __restrict__ W1, const float* __restrict__ W2,
                             const float* __restrict__ W3, const float* __restrict__ W4)
{
    int i = blockIdx.x * blockDim.x + threadIdx.x;
    if (i < NN * HID) g_h[0][i] = 0.0f;
    if (i < NN * EF) g_agg[i] = 0.0f;
    if (i < NITER) g_tctr[i] = 0;
    if (i < WB_ELEMS) {
        const int E1 = WB1_E, E2 = E1 + WB2_E, E3 = E2 + WB2_E;
        const float* W; int e, stride, rows_real, k_real;
        if (i < E1)      { W = W1; e = i;      stride = SB1; rows_real = 96; k_real = 31; }
        else if (i < E2) { W = W2; e = i - E1; stride = SB2; rows_real = 96; k_real = 96; }
        else if (i < E3) { W = W3; e = i - E2; stride = SB2; rows_real = 96; k_real = 96; }
        else             { W = W4; e = i - E3; stride = SB2; rows_real = 11; k_real = 96; }
        int row = e / stride, c = e % stride;
        uint16_t bits = 0;
        if (row < rows_real && c < k_real) {
            __half h = __float2half_rn(W[row * k_real + c]);
            bits = *reinterpret_cast<uint16_t*>(&h);
        }
        g_wb[i] = bits;
    }
}

// Gather one tile's inputs into registers (lane-pair per edge row).
__device__ __forceinline__ void gather_regs(float* x, int myid, int tile, int lane,
                                            const float* __restrict__ hbase,
                                            const float* __restrict__ edge_attr)
{
    int row = lane >> 1, hf = lane & 1;
    int sid = __shfl_sync(0xffffffffu, myid, row);
    int did = __shfl_sync(0xffffffffu, myid, 16 + row);
    const float* hs = hbase + (size_t)sid * HID;
    const float* hd = hbase + (size_t)did * HID;
    if (hf == 0) {
#pragma unroll
        for (int i = 0; i < HID; i++) x[i] = hs[i];
#pragma unroll
        for (int i = 0; i < 6; i++) x[HID + i] = hd[i];
    } else {
#pragma unroll
        for (int i = 0; i < 4; i++) x[i] = hd[6 + i];
#pragma unroll
        for (int i = 0; i < EF; i++)
            x[4 + i] = edge_attr[(size_t)(tile * EWT + row) * EF + i];
        x[15] = 0.0f;
    }
}

// Pack hi/lo fp16 and store one tile's A1 operand.
__device__ __forceinline__ void pack_store(char* smA1, const float* x, int lane)
{
    int row = lane >> 1, hf = lane & 1;
    uint32_t hh[8], ll[8];
#pragma unroll
    for (int p = 0; p < 8; p++) pack_hilo(x[2 * p], x[2 * p + 1], hh[p], ll[p]);
    int cb = hf * 16;
    *(uint4*)(smA1 + (row * SA1 + cb) * 2)          = make_uint4(hh[0], hh[1], hh[2], hh[3]);
    *(uint4*)(smA1 + (row * SA1 + cb + 8) * 2)      = make_uint4(hh[4], hh[5], hh[6], hh[7]);
    *(uint4*)(smA1 + (row * SA1 + 32 + cb) * 2)     = make_uint4(ll[0], ll[1], ll[2], ll[3]);
    *(uint4*)(smA1 + (row * SA1 + 32 + cb + 8) * 2) = make_uint4(ll[4], ll[5], ll[6], ll[7]);
}

// ---------------------------------------------------------------------------
// Persistent warp-autonomous edge MLP, tile-level software pipelining:
// next tile's draw + id loads + gathers overlap current tile's MMA phase.
// ---------------------------------------------------------------------------
__global__ __launch_bounds__(NTHR, 1)
void edge_kernel(int iter, int parity,
                 const float* __restrict__ edge_attr,
                 const int* __restrict__ src, const int* __restrict__ dst,
                 const float* __restrict__ b1, const float* __restrict__ b2,
                 const float* __restrict__ b3, const float* __restrict__ b4)
{
    extern __shared__ char sm[];
    const uint32_t sbase = smem_u32(sm);
    const int tid = threadIdx.x;
    const int wid = tid >> 5, lane = tid & 31;

    float* biasf = (float*)(sm + OFF_BIAS);

    // stage weights + biases ONCE per CTA
    {
        const float4* gw = (const float4*)g_wb;
        float4* sw = (float4*)(sm + OFF_B1);
        for (int i = tid; i < WB_ELEMS / 8; i += NTHR) sw[i] = gw[i];
    }
    if (tid < 96) { biasf[tid] = b1[tid]; biasf[96 + tid] = b2[tid]; biasf[192 + tid] = b3[tid]; }
    if (tid >= 96 && tid < 112) biasf[288 + tid - 96] = (tid - 96 < EF) ? b4[tid - 96] : 0.0f;
    __syncthreads();

    // lane-derived fragment coordinates
    const int am = lane >> 3;
    const int a_r = ((am & 1) << 3) | (lane & 7);
    const int a_k = (am >> 1) << 3;
    const int b_n = ((am >> 1) << 3) | (lane & 7);
    const int b_k = (am & 1) << 3;
    const int q2 = (lane & 3) * 2;
    const int g8 = lane >> 2;

    char* smA1w = sm + OFF_A1 + wid * 2 * A1W_BYTES;
    const uint32_t sbA1w = sbase + OFF_A1 + wid * 2 * A1W_BYTES;
    const float* __restrict__ hbase = g_h[parity];

    // ---- prologue: draw tile 0, gather + pack into buffer 0
    int tile;
    {
        int t0c;
        if (lane == 0) t0c = atomicAdd(&g_tctr[iter], 1);
        tile = __shfl_sync(0xffffffffu, t0c, 0);
    }
    int myid = 0;
    if (tile < TILESW) {
        float x[16];
        myid = (lane < EWT) ? src[tile * EWT + lane] : dst[tile * EWT + lane - EWT];
        gather_regs(x, myid, tile, lane, hbase, edge_attr);
        pack_store(smA1w, x, lane);
    }
    int cur = 0;
    __syncwarp();

    while (tile < TILESW) {
        // ---- prefetch next tile (LDGs in flight during compute below)
        int ntile;
        {
            int t0c;
            if (lane == 0) t0c = atomicAdd(&g_tctr[iter], 1);
            ntile = __shfl_sync(0xffffffffu, t0c, 0);
        }
        int nid = 0;
        float nx[16];
        if (ntile < TILESW) {
            nid = (lane < EWT) ? src[ntile * EWT + lane] : dst[ntile * EWT + lane - EWT];
            gather_regs(nx, nid, ntile, lane, hbase, edge_attr);
        }
        // current tile's scatter ids (before myid is overwritten)
        const int dn0 = __shfl_sync(0xffffffffu, myid, 16 + g8);
        const int dn1 = __shfl_sync(0xffffffffu, myid, 24 + g8);

        const uint32_t sbA1c = sbA1w + cur * A1W_BYTES;

        float d[12][4];

        // ---- Layer 1: A from smem (K=32 hi + 32 lo), B1
        {
#pragma unroll
            for (int j = 0; j < 12; j++) {
                float2 bp = *(float2*)(biasf + 8 * j + q2);
                d[j][0] = bp.x; d[j][1] = bp.y; d[j][2] = bp.x; d[j][3] = bp.y;
            }
            uint32_t a1h[2][4], a1l[2][4];
            const uint32_t aAddr = sbA1c + (a_r * SA1 + a_k) * 2;
#pragma unroll
            for (int ks = 0; ks < 2; ks++) {
                ldsm_x4(a1h[ks][0], a1h[ks][1], a1h[ks][2], a1h[ks][3], aAddr + ks * 32);
                ldsm_x4(a1l[ks][0], a1l[ks][1], a1l[ks][2], a1l[ks][3], aAddr + 64 + ks * 32);
            }
#pragma unroll
            for (int j2 = 0; j2 < 6; j2++) {
#pragma unroll
                for (int ks = 0; ks < 2; ks++) {
                    uint32_t t0, t1, t2, t3;
                    ldsm_x4(t0, t1, t2, t3,
                            sbase + OFF_B1 + ((j2 * 16 + b_n) * SB1 + ks * 16 + b_k) * 2);
                    mma_fp16(d[2 * j2],     a1h[ks][0], a1h[ks][1], a1h[ks][2], a1h[ks][3], t0, t1);
                    mma_fp16(d[2 * j2 + 1], a1h[ks][0], a1h[ks][1], a1h[ks][2], a1h[ks][3], t2, t3);
                    mma_fp16(d[2 * j2],     a1l[ks][0], a1l[ks][1], a1l[ks][2], a1l[ks][3], t0, t1);
                    mma_fp16(d[2 * j2 + 1], a1l[ks][0], a1l[ks][1], a1l[ks][2], a1l[ks][3], t2, t3);
                }
            }
        }

        uint32_t af[24], al[24];

        // ---- convert D -> A frags (relu + fp16 hi/lo), in registers
#pragma unroll
        for (int j = 0; j < 12; j++) {
            float v0 = fmaxf(d[j][0], 0.0f), v1 = fmaxf(d[j][1], 0.0f);
            float v2 = fmaxf(d[j][2], 0.0f), v3 = fmaxf(d[j][3], 0.0f);
            pack_hilo(v0, v1, af[2 * j], al[2 * j]);
            pack_hilo(v2, v3, af[2 * j + 1], al[2 * j + 1]);
        }

        // ---- Layers 2 and 3: A from registers, B from smem
#pragma unroll 1
        for (int L = 0; L < 2; L++) {
            const uint32_t bOff = (L == 0) ? OFF_B2 : OFF_B3;
            const int boff = (L == 0) ? 96 : 192;
#pragma unroll
            for (int j = 0; j < 12; j++) {
                float2 bp = *(float2*)(biasf + boff + 8 * j + q2);
                d[j][0] = bp.x; d[j][1] = bp.y; d[j][2] = bp.x; d[j][3] = bp.y;
            }
#pragma unroll
            for (int j2 = 0; j2 < 6; j2++) {
#pragma unroll
                for (int ks = 0; ks < 6; ks++) {
                    uint32_t t0, t1, t2, t3;
                    ldsm_x4(t0, t1, t2, t3,
                            sbase + bOff + ((j2 * 16 + b_n) * SB2 + ks * 16 + b_k) * 2);
                    mma_fp16(d[2 * j2],     af[4 * ks], af[4 * ks + 1], af[4 * ks + 2], af[4 * ks + 3], t0, t1);
                    mma_fp16(d[2 * j2 + 1], af[4 * ks], af[4 * ks + 1], af[4 * ks + 2], af[4 * ks + 3], t2, t3);
                    mma_fp16(d[2 * j2],     al[4 * ks], al[4 * ks + 1], al[4 * ks + 2], al[4 * ks + 3], t0, t1);
                    mma_fp16(d[2 * j2 + 1], al[4 * ks], al[4 * ks + 1], al[4 * ks + 2], al[4 * ks + 3], t2, t3);
                }
            }
#pragma unroll
            for (int j = 0; j < 12; j++) {
                float v0 = fmaxf(d[j][0], 0.0f), v1 = fmaxf(d[j][1], 0.0f);
                float v2 = fmaxf(d[j][2], 0.0f), v3 = fmaxf(d[j][3], 0.0f);
                pack_hilo(v0, v1, af[2 * j], al[2 * j]);
                pack_hilo(v2, v3, af[2 * j + 1], al[2 * j + 1]);
            }
        }

        // ---- Layer 4: N=16 (11 real), A from registers
        float d4[2][4];
#pragma unroll
        for (int nt = 0; nt < 2; nt++) {
            float2 bp = *(float2*)(biasf + 288 + 8 * nt + q2);
            d4[nt][0] = bp.x; d4[nt][1] = bp.y; d4[nt][2] = bp.x; d4[nt][3] = bp.y;
        }
#pragma unroll
        for (int ks = 0; ks < 6; ks++) {
            uint32_t t0, t1, t2, t3;
            ldsm_x4(t0, t1, t2, t3,
                    sbase + OFF_B4 + (b_n * SB2 + ks * 16 + b_k) * 2);
            mma_fp16(d4[0], af[4 * ks], af[4 * ks + 1], af[4 * ks + 2], af[4 * ks + 3], t0, t1);
            mma_fp16(d4[1], af[4 * ks], af[4 * ks + 1], af[4 * ks + 2], af[4 * ks + 3], t2, t3);
            mma_fp16(d4[0], al[4 * ks], al[4 * ks + 1], al[4 * ks + 2], al[4 * ks + 3], t0, t1);
            mma_fp16(d4[1], al[4 * ks], al[4 * ks + 1], al[4 * ks + 2], al[4 * ks + 3], t2, t3);
        }

        // ---- scatter-add to destination nodes
#pragma unroll
        for (int nt = 0; nt < 2; nt++) {
            int c = nt * 8 + q2;
            if (c < EF) {
                atomicAdd(&g_agg[(size_t)dn0 * EF + c], d4[nt][0]);
                atomicAdd(&g_agg[(size_t)dn1 * EF + c], d4[nt][2]);
            }
            if (c + 1 < EF) {
                atomicAdd(&g_agg[(size_t)dn0 * EF + c + 1], d4[nt][1]);
                atomicAdd(&g_agg[(size_t)dn1 * EF + c + 1], d4[nt][3]);
            }
        }

        // ---- commit next tile's A1 into the other buffer
        if (ntile < TILESW)
            pack_store(sm + OFF_A1 + (wid * 2 + (cur ^ 1)) * A1W_BYTES, nx, lane);
        __syncwarp();

        myid = nid;
        tile = ntile;
        cur ^= 1;
    }
}

// ---------------------------------------------------------------------------
// GRU cell + output head; zeroes g_agg for next iter.
// ---------------------------------------------------------------------------
__global__ void gru_kernel(int parity,
                           const float* __restrict__ node_in,
                           const float* __restrict__ wih,
                           const float* __restrict__ whh,
                           const float* __restrict__ bih,
                           const float* __restrict__ bhh,
                           const float* __restrict__ fw,
                           const float* __restrict__ fb,
                           float* __restrict__ out)
{
    __shared__ float s[600 + 300 + 30 + 30 + 20 + 2];
    int tid = threadIdx.x;
    for (int i = tid; i < 600; i += blockDim.x) s[i] = wih[i];
    for (int i = tid; i < 300; i += blockDim.x) s[600 + i] = whh[i];
    for (int i = tid; i < 30; i += blockDim.x) { s[900 + i] = bih[i]; s[930 + i] = bhh[i]; }
    for (int i = tid; i < 20; i += blockDim.x) s[960 + i] = fw[i];
    for (int i = tid; i < 2; i += blockDim.x) s[980 + i] = fb[i];
    __syncthreads();

    int n = blockIdx.x * blockDim.x + tid;
    if (n >= NN) return;

    const float* __restrict__ hp = g_h[parity] + n * HID;
    float* __restrict__ hn = g_h[1 - parity] + n * HID;

    float x[20], hv[HID];
#pragma unroll
    for (int i = 0; i < EF; i++) { x[i] = g_agg[n * EF + i]; g_agg[n * EF + i] = 0.0f; }
#pragma unroll
    for (int i = 0; i < NIN; i++) x[EF + i] = node_in[n * NIN + i];
#pragma unroll
    for (int i = 0; i < HID; i++) hv[i] = hp[i];

    float gi[30], gh[30];
#pragma unroll
    for (int g = 0; g < 30; g++) {
        float a = s[900 + g];
#pragma unroll
        for (int k = 0; k < 20; k++) a = fmaf(s[g * 20 + k], x[k], a);
        gi[g] = a;
        float b = s[930 + g];
#pragma unroll
        for (int k = 0; k < 10; k++) b = fmaf(s[600 + g * 10 + k], hv[k], b);
        gh[g] = b;
    }

    float hnew[HID];
#pragma unroll
    for (int i = 0; i < HID; i++) {
        float r = 1.0f / (1.0f + expf(-(gi[i] + gh[i])));
        float z = 1.0f / (1.0f + expf(-(gi[10 + i] + gh[10 + i])));
        float nval = tanhf(gi[20 + i] + r * gh[20 + i]);
        float hni = (1.0f - z) * nval + z * hv[i];
        hnew[i] = hni;
        hn[i] = hni;
    }

#pragma unroll
    for (int o = 0; o < 2; o++) {
        float a = s[980 + o];
#pragma unroll
        for (int k = 0; k < HID; k++) a = fmaf(s[960 + o * 10 + k], hnew[k], a);
        out[n * 2 + o] = a;
    }
}

// ---------------------------------------------------------------------------
// Launch
// ---------------------------------------------------------------------------
extern "C" void kernel_launch(void* const* d_in, const int* in_sizes, int n_in,
                              void* d_out, int out_size)
{
    const float* node_in   = (const float*)d_in[0];
    const float* edge_attr = (const float*)d_in[1];
    const float* W1 = (const float*)d_in[2];  const float* b1 = (const float*)d_in[3];
    const float* W2 = (const float*)d_in[4];  const float* b2 = (const float*)d_in[5];
    const float* W3 = (const float*)d_in[6];  const float* b3 = (const float*)d_in[7];
    const float* W4 = (const float*)d_in[8];  const float* b4 = (const float*)d_in[9];
    const float* wih = (const float*)d_in[10]; const float* whh = (const float*)d_in[11];
    const float* bih = (const float*)d_in[12]; const float* bhh = (const float*)d_in[13];
    const float* fw  = (const float*)d_in[14]; const float* fb  = (const float*)d_in[15];
    const int* src = (const int*)d_in[16];
    const int* dst = (const int*)d_in[17];
    float* out = (float*)d_out;

    cudaFuncSetAttribute(edge_kernel,
                         cudaFuncAttributeMaxDynamicSharedMemorySize, SMEM_REQ);

    setup_kernel<<<(NN * EF + 255) / 256, 256>>>(W1, W2, W3, W4);

    for (int t = 0; t < NITER; t++) {
        int p = t & 1;
        edge_kernel<<<NCTA, NTHR, SMEM_REQ>>>(t, p, edge_attr, src, dst,
                                              b1, b2, b3, b4);
        gru_kernel<<<(NN + 127) / 128, 128>>>(p, node_in, wih, whh, bih, bhh,
                                              fw, fb, out + (size_t)t * NN * 2);
    }
}

// round 17
// speedup vs baseline: 1.0207x; 1.0207x over previous
#include <cuda_runtime.h>
#include <cuda_fp16.h>
#include <math.h>
#include <stdint.h>

// Problem constants
#define NN     20000
#define NE     320000
#define HID    10
#define NIN    9
#define EF     11
#define NITER  7
#define EWT    16        // edges per warp-tile
#define TILESW (NE/EWT)  // 20000
#define NTHR   384       // 12 warps, each an independent pipeline
#define NWARP  (NTHR/32)
#define NCTA   148       // persistent CTAs (<= SM count, guaranteed co-resident)

// ---------------- smem layout (byte offsets) -------------------------------
#define SB1       40
#define SB2       104
#define SA1       72     // A1 stride (elements): 144B rows -> conflict-free ldsm
#define B1_BYTES  (96*SB1*2)             // 7680
#define B2_BYTES  (96*SB2*2)             // 19968
#define B4_BYTES  (16*SB2*2)             // 3328
#define OFF_B1    0
#define OFF_B2    (OFF_B1 + B1_BYTES)    // 7680
#define OFF_B3    (OFF_B2 + B2_BYTES)    // 27648
#define OFF_B4    (OFF_B3 + B2_BYTES)    // 47616
#define OFF_BIAS  (OFF_B4 + B4_BYTES)    // 50944 (304 floats)
#define OFF_A1    (OFF_BIAS + 304*4)     // 52160
#define A1W_BYTES (EWT*SA1*2)            // 2304 per warp
#define OFF_IDS   (OFF_A1 + NWARP*A1W_BYTES)   // 79808
#define OFF_GRU   (OFF_IDS + NWARP*32*4)       // 81344 (982 floats)
#define SMEM_REQ  (OFF_GRU + 982*4)            // 85272

// Weight blob (fp16 hi only): B1|B2|B3|B4
#define WB1_E   (96*SB1)
#define WB2_E   (96*SB2)
#define WB_ELEMS (WB1_E + 2*WB2_E + 16*SB2)   // 25472
__device__ __align__(16) uint16_t g_wb[WB_ELEMS];
__device__ float g_h[2][NN * HID];
__device__ float g_agg[NN * EF];
__device__ int   g_tctr[NITER];
__device__ int   g_bar[2 * NITER];

// ------------------------------ helpers ------------------------------------
__device__ __forceinline__ uint32_t smem_u32(const void* p)
{
    uint32_t a;
    asm("{ .reg .u64 t; cvta.to.shared.u64 t, %1; cvt.u32.u64 %0, t; }"
        : "=r"(a) : "l"(p));
    return a;
}

__device__ __forceinline__ void ldsm_x4(uint32_t& r0, uint32_t& r1,
                                        uint32_t& r2, uint32_t& r3, uint32_t a)
{
    asm volatile("ldmatrix.sync.aligned.m8n8.x4.shared.b16 {%0,%1,%2,%3}, [%4];"
                 : "=r"(r0), "=r"(r1), "=r"(r2), "=r"(r3) : "r"(a));
}

__device__ __forceinline__ void mma_fp16(float* d,
                                         uint32_t a0, uint32_t a1, uint32_t a2,
                                         uint32_t a3, uint32_t b0, uint32_t b1)
{
    asm volatile(
        "mma.sync.aligned.m16n8k16.row.col.f32.f16.f16.f32 "
        "{%0,%1,%2,%3},{%4,%5,%6,%7},{%8,%9},{%0,%1,%2,%3};"
        : "+f"(d[0]), "+f"(d[1]), "+f"(d[2]), "+f"(d[3])
        : "r"(a0), "r"(a1), "r"(a2), "r"(a3), "r"(b0), "r"(b1));
}

// fp16 hi/lo split of two floats (low half = first value)
__device__ __forceinline__ void pack_hilo(float a, float b, uint32_t& hw, uint32_t& lw)
{
    __half2 h2 = __floats2half2_rn(a, b);
    float ra = a - __half2float(__low2half(h2));
    float rb = b - __half2float(__high2half(h2));
    __half2 l2 = __floats2half2_rn(ra, rb);
    hw = *reinterpret_cast<uint32_t*>(&h2);
    lw = *reinterpret_cast<uint32_t*>(&l2);
}

// grid-wide barrier (all NCTA CTAs co-resident; unique slot b per use)
__device__ __forceinline__ void grid_bar(int b, int tid)
{
    __syncthreads();
    if (tid == 0) {
        __threadfence();
        atomicAdd(&g_bar[b], 1);
        while (*(volatile int*)&g_bar[b] < NCTA) __nanosleep(64);
        __threadfence();
    }
    __syncthreads();
}

// ---------------------------------------------------------------------------
// Setup: zero state + pack fp16(hi) weights + reset counters/barriers
// ---------------------------------------------------------------------------
__global__ void setup_kernel(const float* __restrict__ W1, const float* __restrict__ W2,
                             const float* __restrict__ W3, const float* __restrict__ W4)
{
    int i = blockIdx.x * blockDim.x + threadIdx.x;
    if (i < NN * HID) g_h[0][i] = 0.0f;
    if (i < NN * EF) g_agg[i] = 0.0f;
    if (i < NITER) g_tctr[i] = 0;
    if (i < 2 * NITER) g_bar[i] = 0;
    if (i < WB_ELEMS) {
        const int E1 = WB1_E, E2 = E1 + WB2_E, E3 = E2 + WB2_E;
        const float* W; int e, stride, rows_real, k_real;
        if (i < E1)      { W = W1; e = i;      stride = SB1; rows_real = 96; k_real = 31; }
        else if (i < E2) { W = W2; e = i - E1; stride = SB2; rows_real = 96; k_real = 96; }
        else if (i < E3) { W = W3; e = i - E2; stride = SB2; rows_real = 96; k_real = 96; }
        else             { W = W4; e = i - E3; stride = SB2; rows_real = 11; k_real = 96; }
        int row = e / stride, c = e % stride;
        uint16_t bits = 0;
        if (row < rows_real && c < k_real) {
            __half h = __float2half_rn(W[row * k_real + c]);
            bits = *reinterpret_cast<uint16_t*>(&h);
        }
        g_wb[i] = bits;
    }
}

// ---------------------------------------------------------------------------
// Fused persistent kernel: 7 x { edge MLP phase -> barrier -> GRU phase -> barrier }
// Edge phase: warp-autonomous 16-edge tiles, fp16 2-pass, register forwarding.
// ---------------------------------------------------------------------------
__global__ __launch_bounds__(NTHR, 1)
void fused_kernel(const float* __restrict__ node_in,
                  const float* __restrict__ edge_attr,
                  const int* __restrict__ src, const int* __restrict__ dst,
                  const float* __restrict__ b1, const float* __restrict__ b2,
                  const float* __restrict__ b3, const float* __restrict__ b4,
                  const float* __restrict__ wih, const float* __restrict__ whh,
                  const float* __restrict__ bih, const float* __restrict__ bhh,
                  const float* __restrict__ fw, const float* __restrict__ fb,
                  float* __restrict__ out)
{
    extern __shared__ char sm[];
    const uint32_t sbase = smem_u32(sm);
    const int tid = threadIdx.x;
    const int wid = tid >> 5, lane = tid & 31;

    float* biasf = (float*)(sm + OFF_BIAS);
    float* s = (float*)(sm + OFF_GRU);

    // stage MLP weights + biases + GRU weights ONCE per kernel
    {
        const float4* gw = (const float4*)g_wb;
        float4* sw = (float4*)(sm + OFF_B1);
        for (int i = tid; i < WB_ELEMS / 8; i += NTHR) sw[i] = gw[i];
    }
    if (tid < 96) { biasf[tid] = b1[tid]; biasf[96 + tid] = b2[tid]; biasf[192 + tid] = b3[tid]; }
    if (tid >= 96 && tid < 112) biasf[288 + tid - 96] = (tid - 96 < EF) ? b4[tid - 96] : 0.0f;
    for (int i = tid; i < 600; i += NTHR) s[i] = wih[i];
    for (int i = tid; i < 300; i += NTHR) s[600 + i] = whh[i];
    if (tid < 30) { s[900 + tid] = bih[tid]; s[930 + tid] = bhh[tid]; }
    if (tid >= 32 && tid < 52) s[960 + tid - 32] = fw[tid - 32];
    if (tid >= 64 && tid < 66) s[980 + tid - 64] = fb[tid - 64];
    __syncthreads();

    // lane-derived fragment coordinates
    const int am = lane >> 3;
    const int a_r = ((am & 1) << 3) | (lane & 7);
    const int a_k = (am >> 1) << 3;
    const int b_n = ((am >> 1) << 3) | (lane & 7);
    const int b_k = (am & 1) << 3;
    const int q2 = (lane & 3) * 2;
    const int g8 = lane >> 2;

    char* smA1 = sm + OFF_A1 + wid * A1W_BYTES;
    const uint32_t sbA1 = sbase + OFF_A1 + wid * A1W_BYTES;
    int* wids = (int*)(sm + OFF_IDS) + wid * 32;
    const int node = blockIdx.x * NTHR + tid;

#pragma unroll 1
    for (int t = 0; t < NITER; t++) {
        const int p = t & 1;
        const float* __restrict__ hbase = g_h[p];

        // ================= EDGE PHASE (R14 loop, verbatim) =================
        while (true) {
            int t0c;
            if (lane == 0) t0c = atomicAdd(&g_tctr[t], 1);
            const int tile = __shfl_sync(0xffffffffu, t0c, 0);
            if (tile >= TILESW) break;
            const int ebase = tile * EWT;

            // ---- ids (per-warp)
            wids[lane] = (lane < EWT) ? src[ebase + lane] : dst[ebase + lane - EWT];
            __syncwarp();

            // ---- gather 16 edges x 31 cols -> A1 [16 x (hi32|lo32)] fp16
            {
                int row = lane >> 1, hf = lane & 1;
                float x[16];
                if (hf == 0) {
                    const float* hs = hbase + (size_t)wids[row] * HID;
                    const float* hd = hbase + (size_t)wids[EWT + row] * HID;
#pragma unroll
                    for (int i = 0; i < HID; i++) x[i] = hs[i];
#pragma unroll
                    for (int i = 0; i < 6; i++) x[HID + i] = hd[i];
                } else {
                    const float* hd = hbase + (size_t)wids[EWT + row] * HID;
#pragma unroll
                    for (int i = 0; i < 4; i++) x[i] = hd[6 + i];
#pragma unroll
                    for (int i = 0; i < EF; i++)
                        x[4 + i] = edge_attr[(size_t)(ebase + row) * EF + i];
                    x[15] = 0.0f;
                }
                uint32_t hh[8], ll[8];
#pragma unroll
                for (int q = 0; q < 8; q++) pack_hilo(x[2 * q], x[2 * q + 1], hh[q], ll[q]);
                int cb = hf * 16;
                *(uint4*)(smA1 + (row * SA1 + cb) * 2)          = make_uint4(hh[0], hh[1], hh[2], hh[3]);
                *(uint4*)(smA1 + (row * SA1 + cb + 8) * 2)      = make_uint4(hh[4], hh[5], hh[6], hh[7]);
                *(uint4*)(smA1 + (row * SA1 + 32 + cb) * 2)     = make_uint4(ll[0], ll[1], ll[2], ll[3]);
                *(uint4*)(smA1 + (row * SA1 + 32 + cb + 8) * 2) = make_uint4(ll[4], ll[5], ll[6], ll[7]);
            }
            __syncwarp();

            float d[12][4];

            // ---- Layer 1: A from smem (K=32 hi + 32 lo), B1
            {
#pragma unroll
                for (int j = 0; j < 12; j++) {
                    float2 bp = *(float2*)(biasf + 8 * j + q2);
                    d[j][0] = bp.x; d[j][1] = bp.y; d[j][2] = bp.x; d[j][3] = bp.y;
                }
                uint32_t a1h[2][4], a1l[2][4];
                const uint32_t aAddr = sbA1 + (a_r * SA1 + a_k) * 2;
#pragma unroll
                for (int ks = 0; ks < 2; ks++) {
                    ldsm_x4(a1h[ks][0], a1h[ks][1], a1h[ks][2], a1h[ks][3], aAddr + ks * 32);
                    ldsm_x4(a1l[ks][0], a1l[ks][1], a1l[ks][2], a1l[ks][3], aAddr + 64 + ks * 32);
                }
#pragma unroll
                for (int j2 = 0; j2 < 6; j2++) {
#pragma unroll
                    for (int ks = 0; ks < 2; ks++) {
                        uint32_t t0, t1, t2, t3;
                        ldsm_x4(t0, t1, t2, t3,
                                sbase + OFF_B1 + ((j2 * 16 + b_n) * SB1 + ks * 16 + b_k) * 2);
                        mma_fp16(d[2 * j2],     a1h[ks][0], a1h[ks][1], a1h[ks][2], a1h[ks][3], t0, t1);
                        mma_fp16(d[2 * j2 + 1], a1h[ks][0], a1h[ks][1], a1h[ks][2], a1h[ks][3], t2, t3);
                        mma_fp16(d[2 * j2],     a1l[ks][0], a1l[ks][1], a1l[ks][2], a1l[ks][3], t0, t1);
                        mma_fp16(d[2 * j2 + 1], a1l[ks][0], a1l[ks][1], a1l[ks][2], a1l[ks][3], t2, t3);
                    }
                }
            }

            uint32_t af[24], al[24];

            // ---- convert D -> A frags (relu + fp16 hi/lo), in registers
#pragma unroll
            for (int j = 0; j < 12; j++) {
                float v0 = fmaxf(d[j][0], 0.0f), v1 = fmaxf(d[j][1], 0.0f);
                float v2 = fmaxf(d[j][2], 0.0f), v3 = fmaxf(d[j][3], 0.0f);
                pack_hilo(v0, v1, af[2 * j], al[2 * j]);
                pack_hilo(v2, v3, af[2 * j + 1], al[2 * j + 1]);
            }

            // ---- Layers 2 and 3: A from registers, B from smem
#pragma unroll 1
            for (int L = 0; L < 2; L++) {
                const uint32_t bOff = (L == 0) ? OFF_B2 : OFF_B3;
                const int boff = (L == 0) ? 96 : 192;
#pragma unroll
                for (int j = 0; j < 12; j++) {
                    float2 bp = *(float2*)(biasf + boff + 8 * j + q2);
                    d[j][0] = bp.x; d[j][1] = bp.y; d[j][2] = bp.x; d[j][3] = bp.y;
                }
#pragma unroll
                for (int j2 = 0; j2 < 6; j2++) {
#pragma unroll
                    for (int ks = 0; ks < 6; ks++) {
                        uint32_t t0, t1, t2, t3;
                        ldsm_x4(t0, t1, t2, t3,
                                sbase + bOff + ((j2 * 16 + b_n) * SB2 + ks * 16 + b_k) * 2);
                        mma_fp16(d[2 * j2],     af[4 * ks], af[4 * ks + 1], af[4 * ks + 2], af[4 * ks + 3], t0, t1);
                        mma_fp16(d[2 * j2 + 1], af[4 * ks], af[4 * ks + 1], af[4 * ks + 2], af[4 * ks + 3], t2, t3);
                        mma_fp16(d[2 * j2],     al[4 * ks], al[4 * ks + 1], al[4 * ks + 2], al[4 * ks + 3], t0, t1);
                        mma_fp16(d[2 * j2 + 1], al[4 * ks], al[4 * ks + 1], al[4 * ks + 2], al[4 * ks + 3], t2, t3);
                    }
                }
#pragma unroll
                for (int j = 0; j < 12; j++) {
                    float v0 = fmaxf(d[j][0], 0.0f), v1 = fmaxf(d[j][1], 0.0f);
                    float v2 = fmaxf(d[j][2], 0.0f), v3 = fmaxf(d[j][3], 0.0f);
                    pack_hilo(v0, v1, af[2 * j], al[2 * j]);
                    pack_hilo(v2, v3, af[2 * j + 1], al[2 * j + 1]);
                }
            }

            // ---- Layer 4: N=16 (11 real), A from registers
            float d4[2][4];
#pragma unroll
            for (int nt = 0; nt < 2; nt++) {
                float2 bp = *(float2*)(biasf + 288 + 8 * nt + q2);
                d4[nt][0] = bp.x; d4[nt][1] = bp.y; d4[nt][2] = bp.x; d4[nt][3] = bp.y;
            }
#pragma unroll
            for (int ks = 0; ks < 6; ks++) {
                uint32_t t0, t1, t2, t3;
                ldsm_x4(t0, t1, t2, t3,
                        sbase + OFF_B4 + (b_n * SB2 + ks * 16 + b_k) * 2);
                mma_fp16(d4[0], af[4 * ks], af[4 * ks + 1], af[4 * ks + 2], af[4 * ks + 3], t0, t1);
                mma_fp16(d4[1], af[4 * ks], af[4 * ks + 1], af[4 * ks + 2], af[4 * ks + 3], t2, t3);
                mma_fp16(d4[0], al[4 * ks], al[4 * ks + 1], al[4 * ks + 2], al[4 * ks + 3], t0, t1);
                mma_fp16(d4[1], al[4 * ks], al[4 * ks + 1], al[4 * ks + 2], al[4 * ks + 3], t2, t3);
            }

            // ---- scatter-add to destination nodes
            {
                int dn0 = wids[EWT + g8];
                int dn1 = wids[EWT + g8 + 8];
#pragma unroll
                for (int nt = 0; nt < 2; nt++) {
                    int c = nt * 8 + q2;
                    if (c < EF) {
                        atomicAdd(&g_agg[(size_t)dn0 * EF + c], d4[nt][0]);
                        atomicAdd(&g_agg[(size_t)dn1 * EF + c], d4[nt][2]);
                    }
                    if (c + 1 < EF) {
                        atomicAdd(&g_agg[(size_t)dn0 * EF + c + 1], d4[nt][1]);
                        atomicAdd(&g_agg[(size_t)dn1 * EF + c + 1], d4[nt][3]);
                    }
                }
            }
            __syncwarp();   // all lanes done with wids/A1 before next tile reuses them
        }

        grid_bar(2 * t, tid);

        // ================= GRU PHASE (static node assignment) ==============
        if (node < NN) {
            const float* __restrict__ hp = g_h[p] + node * HID;
            float* __restrict__ hn = g_h[1 - p] + node * HID;

            float x[20], hv[HID];
#pragma unroll
            for (int i = 0; i < EF; i++) { x[i] = g_agg[node * EF + i]; g_agg[node * EF + i] = 0.0f; }
#pragma unroll
            for (int i = 0; i < NIN; i++) x[EF + i] = node_in[node * NIN + i];
#pragma unroll
            for (int i = 0; i < HID; i++) hv[i] = hp[i];

            float gi[30], gh[30];
#pragma unroll
            for (int g = 0; g < 30; g++) {
                float a = s[900 + g];
#pragma unroll
                for (int k = 0; k < 20; k++) a = fmaf(s[g * 20 + k], x[k], a);
                gi[g] = a;
                float b = s[930 + g];
#pragma unroll
                for (int k = 0; k < 10; k++) b = fmaf(s[600 + g * 10 + k], hv[k], b);
                gh[g] = b;
            }

            float hnew[HID];
#pragma unroll
            for (int i = 0; i < HID; i++) {
                float r = 1.0f / (1.0f + expf(-(gi[i] + gh[i])));
                float z = 1.0f / (1.0f + expf(-(gi[10 + i] + gh[10 + i])));
                float nval = tanhf(gi[20 + i] + r * gh[20 + i]);
                float hni = (1.0f - z) * nval + z * hv[i];
                hnew[i] = hni;
                hn[i] = hni;
            }

            float* o = out + (size_t)t * NN * 2 + node * 2;
#pragma unroll
            for (int oo = 0; oo < 2; oo++) {
                float a = s[980 + oo];
#pragma unroll
                for (int k = 0; k < HID; k++) a = fmaf(s[960 + oo * 10 + k], hnew[k], a);
                o[oo] = a;
            }
        }

        grid_bar(2 * t + 1, tid);
    }
}

// ---------------------------------------------------------------------------
// Launch
// ---------------------------------------------------------------------------
extern "C" void kernel_launch(void* const* d_in, const int* in_sizes, int n_in,
                              void* d_out, int out_size)
{
    const float* node_in   = (const float*)d_in[0];
    const float* edge_attr = (const float*)d_in[1];
    const float* W1 = (const float*)d_in[2];  const float* b1 = (const float*)d_in[3];
    const float* W2 = (const float*)d_in[4];  const float* b2 = (const float*)d_in[5];
    const float* W3 = (const float*)d_in[6];  const float* b3 = (const float*)d_in[7];
    const float* W4 = (const float*)d_in[8];  const float* b4 = (const float*)d_in[9];
    const float* wih = (const float*)d_in[10]; const float* whh = (const float*)d_in[11];
    const float* bih = (const float*)d_in[12]; const float* bhh = (const float*)d_in[13];
    const float* fw  = (const float*)d_in[14]; const float* fb  = (const float*)d_in[15];
    const int* src = (const int*)d_in[16];
    const int* dst = (const int*)d_in[17];
    float* out = (float*)d_out;

    cudaFuncSetAttribute(fused_kernel,
                         cudaFuncAttributeMaxDynamicSharedMemorySize, SMEM_REQ);

    setup_kernel<<<(NN * EF + 255) / 256, 256>>>(W1, W2, W3, W4);

    fused_kernel<<<NCTA, NTHR, SMEM_REQ>>>(node_in, edge_attr, src, dst,
                                           b1, b2, b3, b4,
                                           wih, whh, bih, bhh, fw, fb, out);
}